// round 8
// baseline (speedup 1.0000x reference)
#include <cuda_runtime.h>
#include <math.h>

// z: (16, 10, 64, 64) f32.  B=16, C=10 bits, HW=4096, NPIX=65536, NELEM=655360.
// Output layout (f32, concatenated in reference tuple order):
//   [0, 655360)        z_quantized (b,c,h,w)  = sign(z) in {-1,+1}
//   [655360]           loss
//   [655361]           per_sample_entropy
//   [655362, 720898)   min_encoding_indices (b,h,w) cast to float

#define NPIX      65536
#define NELEM     655360
#define OFF_LOSS  655360
#define OFF_PSE   655361
#define OFF_IDX   655362

__device__ float g_avg[1024];
__device__ float g_commit;
__device__ float g_ent;

__global__ void k_init() {
    int t = blockIdx.x * blockDim.x + threadIdx.x;
    if (t < 1024) g_avg[t] = 0.0f;
    if (t == 0) { g_commit = 0.0f; g_ent = 0.0f; }
}

// Elementwise pass: sign quantization, index packing, commitment-loss partial,
// per-sample-entropy partial (sum of 10 binary entropies, since the 1024-way
// softmax factorizes into independent per-bit Bernoullis).
__global__ void __launch_bounds__(256) k_elem(const float* __restrict__ z,
                                              float* __restrict__ out) {
    int pix = blockIdx.x * blockDim.x + threadIdx.x;   // [0, 65536)
    int b = pix >> 12, hw = pix & 4095;
    const float* zp = z + b * 40960 + hw;
    float* op = out + b * 40960 + hw;

    int idx = 0;
    float commit = 0.0f, H = 0.0f;
    #pragma unroll
    for (int c = 0; c < 10; c++) {
        float v = zp[c * 4096];
        bool s = (v > 0.0f);
        float sg = s ? 1.0f : -1.0f;
        op[c * 4096] = sg;
        idx |= ((int)s) << c;
        float d = sg - v;
        commit += d * d;
        // binary entropy of q = sigmoid(400*v):
        // H2 = log1p(e^{-t}) + t*e^{-t}/(1+e^{-t}), t = |400 v|
        float t = 400.0f * fabsf(v);
        float e = __expf(-t);
        H += log1pf(e) + t * e / (1.0f + e);
    }
    out[OFF_IDX + pix] = (float)idx;

    // warp-reduce the two scalars
    #pragma unroll
    for (int o = 16; o; o >>= 1) {
        commit += __shfl_down_sync(0xffffffffu, commit, o);
        H      += __shfl_down_sync(0xffffffffu, H, o);
    }
    if ((threadIdx.x & 31) == 0) {
        atomicAdd(&g_commit, commit);
        atomicAdd(&g_ent, H);
    }
}

// avg_probs: sum over pixels of p_n for all n in [0,1024).
// p_n = prod_c (bit ? q_c : 1-q_c), q_c = sigmoid(400 z_c).
// Split 10 bits -> lo (bits 0-4, 32 subset products) x hi (bits 5-9):
// p_n = lo[n&31] * hi[n>>5].  Each thread owns 4 codes (n = tid + 256k) and
// accumulates in registers over the block's 128 pixels; one atomicAdd per code.
__global__ void __launch_bounds__(256) k_probs(const float* __restrict__ z) {
    __shared__ float qb[128][10];
    __shared__ float lo[16][32];
    __shared__ __align__(16) float hiT[16][32];

    int tid = threadIdx.x;
    int pix0 = blockIdx.x * 128;

    // Fill q-buffer: 1280 values, 5 per thread, c-major so global loads coalesce.
    #pragma unroll
    for (int k = 0; k < 5; k++) {
        int v = tid + k * 256;          // [0,1280)
        int c = v >> 7, p = v & 127;
        int pix = pix0 + p;
        int b = pix >> 12, hw = pix & 4095;
        float zv = z[b * 40960 + c * 4096 + hw];
        qb[p][c] = 1.0f / (1.0f + __expf(-400.0f * zv));   // saturates cleanly to 0/1
    }
    __syncthreads();

    float a0 = 0.0f, a1 = 0.0f, a2 = 0.0f, a3 = 0.0f;
    int lane5 = tid & 31, grp = tid >> 5;

    for (int s = 0; s < 8; s++) {           // 8 stages x 16 pixels = 128 pixels
        // Phase B: 16 pixels * 64 subset entries = 1024; 4 per thread.
        #pragma unroll
        for (int j = 0; j < 4; j++) {
            int e = tid + j * 256;
            int pl = e >> 6;                // local pixel 0..15
            int i = e & 31;                 // subset index
            int half = (e >> 5) & 1;        // 0: bits 0-4, 1: bits 5-9
            int c0 = half * 5;
            int row = s * 16 + pl;
            float prod = 1.0f;
            #pragma unroll
            for (int k = 0; k < 5; k++) {
                float q = qb[row][c0 + k];
                prod *= ((i >> k) & 1) ? q : (1.0f - q);
            }
            if (half)
                // permute so phase C reads hi[(tid>>5)+8k] as a contiguous float4
                hiT[pl][((i & 7) << 2) | (i >> 3)] = prod;
            else
                lo[pl][i] = prod;
        }
        __syncthreads();

        // Phase C: acc[k] covers n = tid + 256k.
        // n&31 = lane5 (one conflict-free LDS), n>>5 = grp + 8k (one broadcast
        // float4 LDS), 4 FMA per pixel.
        #pragma unroll
        for (int pl = 0; pl < 16; pl++) {
            float lv = lo[pl][lane5];
            float4 hv = *(const float4*)&hiT[pl][grp * 4];
            a0 += lv * hv.x;
            a1 += lv * hv.y;
            a2 += lv * hv.z;
            a3 += lv * hv.w;
        }
        __syncthreads();
    }

    atomicAdd(&g_avg[tid],       a0);
    atomicAdd(&g_avg[tid + 256], a1);
    atomicAdd(&g_avg[tid + 512], a2);
    atomicAdd(&g_avg[tid + 768], a3);
}

__global__ void k_final(float* __restrict__ out) {
    __shared__ float red[8];
    int tid = threadIdx.x;   // 256 threads
    float s = 0.0f;
    #pragma unroll
    for (int k = 0; k < 4; k++) {
        float ap = g_avg[tid + 256 * k] * (1.0f / 65536.0f);
        s += -ap * logf(ap + 1e-5f);
    }
    #pragma unroll
    for (int o = 16; o; o >>= 1) s += __shfl_down_sync(0xffffffffu, s, o);
    if ((tid & 31) == 0) red[tid >> 5] = s;
    __syncthreads();
    if (tid < 32) {
        float v = (tid < 8) ? red[tid] : 0.0f;
        #pragma unroll
        for (int o = 4; o; o >>= 1) v += __shfl_down_sync(0xffffffffu, v, o);
        if (tid == 0) {
            float avg_entropy = v;                                // gamma = 1.0
            float pse = g_ent * (1.0f / 65536.0f);
            float commit = 0.25f * g_commit * (1.0f / 655360.0f);
            float entropy_loss = 0.1f * (pse - avg_entropy);
            out[OFF_LOSS] = commit + entropy_loss;
            out[OFF_PSE]  = pse;
        }
    }
}

extern "C" void kernel_launch(void* const* d_in, const int* in_sizes, int n_in,
                              void* d_out, int out_size) {
    const float* z = (const float*)d_in[0];
    float* out = (float*)d_out;
    (void)in_sizes; (void)n_in; (void)out_size;
    k_init<<<4, 256>>>();
    k_elem<<<256, 256>>>(z, out);
    k_probs<<<512, 256>>>(z);
    k_final<<<1, 256>>>(out);
}

// round 10
// speedup vs baseline: 1.5405x; 1.5405x over previous
#include <cuda_runtime.h>
#include <math.h>

// z: (16, 10, 64, 64) f32.  B=16, C=10 bits, HW=4096, NPIX=65536, NELEM=655360.
// Output layout (f32, concatenated in reference tuple order):
//   [0, 655360)        z_quantized (b,c,h,w)  = sign(z) in {-1,+1}
//   [655360]           loss
//   [655361]           per_sample_entropy
//   [655362, 720898)   min_encoding_indices (b,h,w) cast to float

#define OFF_LOSS  655360
#define OFF_PSE   655361
#define OFF_IDX   655362

__device__ float    g_avg[1024];
__device__ float    g_commit;
__device__ float    g_ent;
__device__ unsigned g_count;

// Single fused kernel:
//  - elementwise: sign quantization, index packing, commitment partial,
//    per-sample entropy partial (sum of 10 binary entropies: the 1024-way
//    softmax factorizes into independent per-bit Bernoullis)
//  - avg_probs: p_n = lo[n&31] * hi[n>>5] subset-product split; per-thread
//    register accumulators over the block's 128 pixels, one atomicAdd/code
//  - last block (ticket) computes avg_entropy + loss scalars and resets the
//    global accumulators so every graph replay starts from zero.
__global__ void __launch_bounds__(256) k_fused(const float* __restrict__ z,
                                               float* __restrict__ out) {
    __shared__ float qb[128][10];
    __shared__ float lo[16][32];
    __shared__ __align__(16) float hiT[16][32];
    __shared__ float s_red[8];
    __shared__ unsigned s_ticket;

    int tid = threadIdx.x;
    int pix0 = blockIdx.x * 128;

    // ---- Load + elementwise pass (coalesced, c-major) ----
    float commit = 0.0f, H = 0.0f;
    #pragma unroll
    for (int k = 0; k < 5; k++) {
        int v = tid + k * 256;          // [0,1280)
        int c = v >> 7, p = v & 127;
        int pix = pix0 + p;
        int b = pix >> 12, hw = pix & 4095;
        int off = b * 40960 + c * 4096 + hw;
        float zv = z[off];
        bool s = (zv > 0.0f);
        float sg = s ? 1.0f : -1.0f;
        out[off] = sg;                  // z_quantized
        float d = sg - zv;
        commit += d * d;
        // binary entropy of q = sigmoid(400*zv):
        // H2 = log1p(e) + t*e/(1+e), t = |400 zv|, e = exp(-t)
        float t = 400.0f * fabsf(zv);
        float e = __expf(-t);
        float inv = 1.0f / (1.0f + e);
        H += log1pf(e) + t * e * inv;
        // sigmoid(400*zv) without overflow: v>0 -> 1/(1+e), v<=0 -> e/(1+e)
        qb[p][c] = s ? inv : e * inv;
    }
    __syncthreads();

    // ---- Index packing (q > 0.5  <=>  z > 0, incl. z==0 -> false) ----
    if (tid < 128) {
        int idx = 0;
        #pragma unroll
        for (int c = 0; c < 10; c++) idx |= ((int)(qb[tid][c] > 0.5f)) << c;
        out[OFF_IDX + pix0 + tid] = (float)idx;
    }

    // ---- Reduce commit / per-sample entropy partials ----
    #pragma unroll
    for (int o = 16; o; o >>= 1) {
        commit += __shfl_down_sync(0xffffffffu, commit, o);
        H      += __shfl_down_sync(0xffffffffu, H, o);
    }
    if ((tid & 31) == 0) {
        atomicAdd(&g_commit, commit);
        atomicAdd(&g_ent, H);
    }

    // ---- avg_probs via subset-product split ----
    float a0 = 0.0f, a1 = 0.0f, a2 = 0.0f, a3 = 0.0f;
    int lane5 = tid & 31, grp = tid >> 5;

    for (int s = 0; s < 8; s++) {           // 8 stages x 16 pixels = 128 pixels
        // Phase B: 16 pixels * 64 subset entries = 1024; 4 per thread.
        #pragma unroll
        for (int j = 0; j < 4; j++) {
            int e = tid + j * 256;
            int pl = e >> 6;                // local pixel 0..15
            int i = e & 31;                 // subset index
            int half = (e >> 5) & 1;        // 0: bits 0-4, 1: bits 5-9
            int c0 = half * 5;
            int row = s * 16 + pl;
            float prod = 1.0f;
            #pragma unroll
            for (int k = 0; k < 5; k++) {
                float q = qb[row][c0 + k];
                prod *= ((i >> k) & 1) ? q : (1.0f - q);
            }
            if (half)
                // permute so phase C reads hi[grp + 8k] as a contiguous float4
                hiT[pl][((i & 7) << 2) | (i >> 3)] = prod;
            else
                lo[pl][i] = prod;
        }
        __syncthreads();

        // Phase C: acc[k] covers n = tid + 256k.
        // n&31 = lane5 (conflict-free LDS), n>>5 = grp + 8k (broadcast float4).
        #pragma unroll
        for (int pl = 0; pl < 16; pl++) {
            float lv = lo[pl][lane5];
            float4 hv = *(const float4*)&hiT[pl][grp * 4];
            a0 += lv * hv.x;
            a1 += lv * hv.y;
            a2 += lv * hv.z;
            a3 += lv * hv.w;
        }
        __syncthreads();
    }

    atomicAdd(&g_avg[tid],       a0);
    atomicAdd(&g_avg[tid + 256], a1);
    atomicAdd(&g_avg[tid + 512], a2);
    atomicAdd(&g_avg[tid + 768], a3);

    // ---- Last-block finalization (single-launch, no separate init/final) ----
    __threadfence();
    __syncthreads();
    if (tid == 0) s_ticket = atomicAdd(&g_count, 1u);
    __syncthreads();

    if (s_ticket == gridDim.x - 1) {        // uniform per block: syncs are legal
        __threadfence();
        float ssum = 0.0f;
        #pragma unroll
        for (int k = 0; k < 4; k++) {
            float ap = g_avg[tid + 256 * k] * (1.0f / 65536.0f);
            ssum += -ap * logf(ap + 1e-5f);
            g_avg[tid + 256 * k] = 0.0f;    // reset for next graph replay
        }
        #pragma unroll
        for (int o = 16; o; o >>= 1) ssum += __shfl_down_sync(0xffffffffu, ssum, o);
        if ((tid & 31) == 0) s_red[tid >> 5] = ssum;
        __syncthreads();
        if (tid < 32) {
            float v = (tid < 8) ? s_red[tid] : 0.0f;
            #pragma unroll
            for (int o = 4; o; o >>= 1) v += __shfl_down_sync(0xffffffffu, v, o);
            if (tid == 0) {
                float avg_entropy = v;                             // gamma = 1.0
                float pse = g_ent * (1.0f / 65536.0f);
                float cm  = 0.25f * g_commit * (1.0f / 655360.0f);
                out[OFF_LOSS] = cm + 0.1f * (pse - avg_entropy);
                out[OFF_PSE]  = pse;
                g_commit = 0.0f; g_ent = 0.0f; g_count = 0u;       // reset
            }
        }
    }
}

extern "C" void kernel_launch(void* const* d_in, const int* in_sizes, int n_in,
                              void* d_out, int out_size) {
    const float* z = (const float*)d_in[0];
    float* out = (float*)d_out;
    (void)in_sizes; (void)n_in; (void)out_size;
    k_fused<<<512, 256>>>(z, out);
}